// round 9
// baseline (speedup 1.0000x reference)
#include <cuda_runtime.h>
#include <cstdint>

#define M_TOK 4096
#define HDIM  4096
#define IDIM  14336

#define L2F (1.0f/254.0f)
#define L3F (1.0f/(254.0f*254.0f))

// ---------------------------------------------------------------------------
// Device scratch (allocation-free rule)
// ---------------------------------------------------------------------------
__device__ int8_t g_xq8[(size_t)M_TOK * HDIM];
__device__ float  g_xscale[M_TOK];
__device__ float  g_sgate[(size_t)M_TOK * IDIM];   // silu(gate), fp32
__device__ float  g_inter[(size_t)M_TOK * IDIM];   // silu(gate)*up
__device__ int8_t g_q28[(size_t)M_TOK * IDIM];
__device__ float  g_s2[M_TOK];
__device__ int8_t g_wg1[(size_t)IDIM * HDIM], g_wg2[(size_t)IDIM * HDIM], g_wg3[(size_t)IDIM * HDIM];
__device__ int8_t g_wu1[(size_t)IDIM * HDIM], g_wu2[(size_t)IDIM * HDIM], g_wu3[(size_t)IDIM * HDIM];
__device__ int8_t g_wd1[(size_t)HDIM * IDIM], g_wd2[(size_t)HDIM * IDIM], g_wd3[(size_t)HDIM * IDIM];
__device__ float  g_wgs[IDIM], g_wus[IDIM], g_wds[HDIM];

// ---------------------------------------------------------------------------
// PTX helpers (legal at compute_103 base target)
// ---------------------------------------------------------------------------
__device__ __forceinline__ uint32_t smem_u32(const void* p) {
    uint32_t a;
    asm("{ .reg .u64 t; cvta.to.shared.u64 t, %1; cvt.u32.u64 %0, t; }" : "=r"(a) : "l"(p));
    return a;
}
__device__ __forceinline__ void cp_async16(uint32_t saddr, const void* g) {
    asm volatile("cp.async.cg.shared.global [%0], [%1], 16;\n" :: "r"(saddr), "l"(g));
}
__device__ __forceinline__ void cp_commit() { asm volatile("cp.async.commit_group;\n"); }
template<int N> __device__ __forceinline__ void cp_wait() {
    asm volatile("cp.async.wait_group %0;\n" :: "n"(N));
}
__device__ __forceinline__ void ldsm_x4(uint32_t* r, uint32_t addr) {
    asm volatile("ldmatrix.sync.aligned.m8n8.x4.shared.b16 {%0,%1,%2,%3}, [%4];"
                 : "=r"(r[0]), "=r"(r[1]), "=r"(r[2]), "=r"(r[3]) : "r"(addr));
}
__device__ __forceinline__ void imma16832(int* c, const uint32_t* a, uint32_t b0, uint32_t b1) {
    asm volatile(
        "mma.sync.aligned.m16n8k32.row.col.s32.s8.s8.s32 "
        "{%0,%1,%2,%3},{%4,%5,%6,%7},{%8,%9},{%0,%1,%2,%3};\n"
        : "+r"(c[0]), "+r"(c[1]), "+r"(c[2]), "+r"(c[3])
        : "r"(a[0]), "r"(a[1]), "r"(a[2]), "r"(a[3]), "r"(b0), "r"(b1));
}
__device__ __forceinline__ float silu_f(float g) {
    return __fdividef(g, 1.f + expf(-g));
}
// int8 tile: 128 rows x 64B; row pairs share a 128B line; 16B slot XOR-swizzled.
__device__ __forceinline__ uint32_t tile_off(int r, int c) {
    return (uint32_t)((r >> 1) * 128 + (((r & 1) * 4 + (c ^ ((r >> 1) & 3))) << 4));
}

// ---------------------------------------------------------------------------
// int8 3-level NT GEMM: val = rowscale[m]*ws1[n]*(P1 + P2/254 + P3/254^2)
// P_L = A(int8)[M,K] @ B_L(int8)[N,K]^T, exact int32 accumulation.
// 128x128x64 tile, 3-stage cp.async, 8 warps (4m x 2n), warp 32x64.
// MODE: 0 = store val; 1 = store silu(val); 2 = store gateIn*val
// ---------------------------------------------------------------------------
template<int MODE>
__global__ void __launch_bounds__(256, 1)
igemm_kernel(const int8_t* __restrict__ A,
             const int8_t* __restrict__ B1,
             const int8_t* __restrict__ B2,
             const int8_t* __restrict__ B3,
             const float* __restrict__ ws1,
             const float* __restrict__ rowscale,
             const float* __restrict__ gateIn,
             float* __restrict__ Cout,
             int K, int N)
{
    constexpr int TILE  = 8192;          // 128 rows * 64B
    constexpr int STAGE = 4 * TILE;      // A + 3 B levels = 32KB
    constexpr int NSTG  = 3;

    extern __shared__ char smem_raw[];
    const uint32_t sb = (smem_u32(smem_raw) + 127u) & ~127u;

    const int tid  = threadIdx.x;
    const int warp = tid >> 5;
    const int lane = tid & 31;
    const int wm = warp & 3;
    const int wn = warp >> 2;
    const int bm = blockIdx.x * 128;
    const int bn = blockIdx.y * 128;

    int acc[3][2][8][4];
    #pragma unroll
    for (int L = 0; L < 3; L++)
        #pragma unroll
        for (int a = 0; a < 2; a++)
            #pragma unroll
            for (int b = 0; b < 8; b++)
                #pragma unroll
                for (int c = 0; c < 4; c++) acc[L][a][b][c] = 0;

    const int KT = K >> 6;

    // loader: each thread owns 2 (row, 16B-chunk) slots per 8KB tile
    const int lr = tid >> 2;          // 0..63
    const int lc = tid & 3;
    const uint32_t so0 = tile_off(lr, lc);
    const uint32_t so1 = tile_off(lr + 64, lc);
    const size_t row64 = (size_t)64 * K;
    const int8_t* gA  = A  + (size_t)(bm + lr) * K + lc * 16;
    const int8_t* gB1 = B1 + (size_t)(bn + lr) * K + lc * 16;
    const int8_t* gB2 = B2 + (size_t)(bn + lr) * K + lc * 16;
    const int8_t* gB3 = B3 + (size_t)(bn + lr) * K + lc * 16;

    auto load_stage = [&](int kt, int s) {
        const int ko = kt * 64;
        const uint32_t st = sb + s * STAGE;
        cp_async16(st +            so0, gA  + ko);
        cp_async16(st +            so1, gA  + row64 + ko);
        cp_async16(st +     TILE + so0, gB1 + ko);
        cp_async16(st +     TILE + so1, gB1 + row64 + ko);
        cp_async16(st + 2 * TILE + so0, gB2 + ko);
        cp_async16(st + 2 * TILE + so1, gB2 + row64 + ko);
        cp_async16(st + 3 * TILE + so0, gB3 + ko);
        cp_async16(st + 3 * TILE + so1, gB3 + row64 + ko);
    };

    // ldmatrix lane addressing (s8 m16n8k32 fragment layout)
    const int la7 = lane & 7;
    const int kselA = lane >> 4;          // A: 16B k-chunk from bit4
    const int kselB = (lane >> 3) & 1;    // B: 16B k-chunk from bit3
    uint32_t aterm[2]; int axor[2];
    #pragma unroll
    for (int mi = 0; mi < 2; mi++) {
        int rA = wm * 32 + mi * 16 + la7 + ((lane >> 3) & 1) * 8;
        aterm[mi] = (uint32_t)((rA >> 1) * 128 + (rA & 1) * 64);
        axor[mi]  = (rA >> 1) & 3;
    }
    uint32_t bterm[4]; int bxor[4];
    #pragma unroll
    for (int p = 0; p < 4; p++) {
        int rB = wn * 64 + p * 16 + la7 + (lane >> 4) * 8;
        bterm[p] = (uint32_t)((rB >> 1) * 128 + (rB & 1) * 64);
        bxor[p]  = (rB >> 1) & 3;
    }

    load_stage(0, 0); cp_commit();
    load_stage(1, 1); cp_commit();

    for (int kt = 0; kt < KT; kt++) {
        cp_wait<1>();
        __syncthreads();
        if (kt + 2 < KT) load_stage(kt + 2, (kt + 2) % NSTG);
        cp_commit();

        const uint32_t base = sb + (kt % NSTG) * STAGE;
        #pragma unroll
        for (int kk = 0; kk < 2; kk++) {            // two k32 steps
            uint32_t afr[2][4];
            const int cA = kk * 2 + kselA;
            ldsm_x4(afr[0], base + aterm[0] + (uint32_t)((cA ^ axor[0]) << 4));
            ldsm_x4(afr[1], base + aterm[1] + (uint32_t)((cA ^ axor[1]) << 4));
            const int cB = kk * 2 + kselB;
            #pragma unroll
            for (int p = 0; p < 4; p++) {
                const uint32_t boff = bterm[p] + (uint32_t)((cB ^ bxor[p]) << 4);
                #pragma unroll
                for (int L = 0; L < 3; L++) {
                    uint32_t bfr[4];
                    ldsm_x4(bfr, base + (1 + L) * TILE + boff);
                    imma16832(acc[L][0][2 * p],     afr[0], bfr[0], bfr[1]);
                    imma16832(acc[L][1][2 * p],     afr[1], bfr[0], bfr[1]);
                    imma16832(acc[L][0][2 * p + 1], afr[0], bfr[2], bfr[3]);
                    imma16832(acc[L][1][2 * p + 1], afr[1], bfr[2], bfr[3]);
                }
            }
        }
    }

    // epilogue
    const int gr = lane >> 2;
    const int gc = (lane & 3) * 2;
    #pragma unroll
    for (int mi = 0; mi < 2; mi++) {
        const int r0 = bm + wm * 32 + mi * 16 + gr;
        const float rs0 = rowscale[r0];
        const float rs1 = rowscale[r0 + 8];
        #pragma unroll
        for (int ni = 0; ni < 8; ni++) {
            const int col = bn + wn * 64 + ni * 8 + gc;
            const float2 ws = *(const float2*)&ws1[col];
            float f0 = (float)acc[0][mi][ni][0] + L2F * (float)acc[1][mi][ni][0] + L3F * (float)acc[2][mi][ni][0];
            float f1 = (float)acc[0][mi][ni][1] + L2F * (float)acc[1][mi][ni][1] + L3F * (float)acc[2][mi][ni][1];
            float f2 = (float)acc[0][mi][ni][2] + L2F * (float)acc[1][mi][ni][2] + L3F * (float)acc[2][mi][ni][2];
            float f3 = (float)acc[0][mi][ni][3] + L2F * (float)acc[1][mi][ni][3] + L3F * (float)acc[2][mi][ni][3];
            float v0 = rs0 * ws.x * f0;
            float v1 = rs0 * ws.y * f1;
            float v2 = rs1 * ws.x * f2;
            float v3 = rs1 * ws.y * f3;
            if (MODE == 1) {
                v0 = silu_f(v0); v1 = silu_f(v1); v2 = silu_f(v2); v3 = silu_f(v3);
            } else if (MODE == 2) {
                const float2 ga = *(const float2*)&gateIn[(size_t)r0 * N + col];
                const float2 gb = *(const float2*)&gateIn[(size_t)(r0 + 8) * N + col];
                v0 *= ga.x; v1 *= ga.y; v2 *= gb.x; v3 *= gb.y;
            }
            *(float2*)&Cout[(size_t)r0 * N + col]       = make_float2(v0, v1);
            *(float2*)&Cout[(size_t)(r0 + 8) * N + col] = make_float2(v2, v3);
        }
    }
}

// ---------------------------------------------------------------------------
// Block max-reduce
// ---------------------------------------------------------------------------
__device__ __forceinline__ float block_max(float v, float* red) {
    #pragma unroll
    for (int o = 16; o; o >>= 1) v = fmaxf(v, __shfl_xor_sync(0xFFFFFFFFu, v, o));
    if ((threadIdx.x & 31) == 0) red[threadIdx.x >> 5] = v;
    __syncthreads();
    if (threadIdx.x < 32) {
        float w = (threadIdx.x < (blockDim.x >> 5)) ? red[threadIdx.x] : 0.f;
        #pragma unroll
        for (int o = 16; o; o >>= 1) w = fmaxf(w, __shfl_xor_sync(0xFFFFFFFFu, w, o));
        if (threadIdx.x == 0) red[0] = w;
    }
    __syncthreads();
    return red[0];
}

// ---------------------------------------------------------------------------
// Weight split: per-row 3-level int8 expansion. w = s1*(q1 + q2/254 + q3/254^2)
// one block per output row; row cached in dynamic smem
// ---------------------------------------------------------------------------
__global__ void split3_kernel(const float* __restrict__ W,
                              int8_t* __restrict__ q1, int8_t* __restrict__ q2,
                              int8_t* __restrict__ q3, float* __restrict__ s1arr,
                              int K) {
    extern __shared__ float row[];
    __shared__ float red[32];
    const int n = blockIdx.x;
    const float4* wr = (const float4*)(W + (size_t)n * K);
    float amax = 0.f;
    for (int i = threadIdx.x; i < K / 4; i += blockDim.x) {
        float4 v = wr[i];
        ((float4*)row)[i] = v;
        amax = fmaxf(amax, fmaxf(fmaxf(fabsf(v.x), fabsf(v.y)), fmaxf(fabsf(v.z), fabsf(v.w))));
    }
    __syncthreads();
    amax = block_max(amax, red);
    amax = fmaxf(amax, 1e-30f);
    if (threadIdx.x == 0) s1arr[n] = amax * (1.0f / 127.0f);
    const float inv = 127.0f / amax;
    for (int i = threadIdx.x; i < K; i += blockDim.x) {
        float w = row[i] * inv;                 // |w| <= 127
        float f1 = rintf(w);
        float r1 = w - f1;                      // [-0.5, 0.5]
        float f2 = rintf(r1 * 254.f);
        float r2 = r1 * 254.f - f2;
        float f3 = rintf(r2 * 254.f);
        const size_t o = (size_t)n * K + i;
        q1[o] = (int8_t)(int)f1;
        q2[o] = (int8_t)(int)f2;
        q3[o] = (int8_t)(int)f3;
    }
}

// ---------------------------------------------------------------------------
// Per-token fake-quant of x -> int8
// ---------------------------------------------------------------------------
__global__ void quant_x_kernel(const float* __restrict__ x) {
    __shared__ float red[32];
    __shared__ float row[HDIM];
    const int t = blockIdx.x;
    const float4* xr = (const float4*)(x + (size_t)t * HDIM);
    float amax = 0.f;
    for (int i = threadIdx.x; i < HDIM / 4; i += blockDim.x) {
        float4 v = xr[i];
        ((float4*)row)[i] = v;
        amax = fmaxf(amax, fmaxf(fmaxf(fabsf(v.x), fabsf(v.y)), fmaxf(fabsf(v.z), fabsf(v.w))));
    }
    __syncthreads();
    amax = block_max(amax, red);
    const float scale = fmaxf(amax * (1.0f / 127.0f), 1e-8f);
    if (threadIdx.x == 0) g_xscale[t] = scale;
    const float inv = 1.0f / scale;
    for (int i = threadIdx.x; i < HDIM; i += blockDim.x) {
        float q = rintf(row[i] * inv);
        q = fminf(fmaxf(q, -128.f), 127.f);
        g_xq8[(size_t)t * HDIM + i] = (int8_t)(int)q;
    }
}

// ---------------------------------------------------------------------------
// Per-token fake-quant of inter -> int8
// ---------------------------------------------------------------------------
__global__ void quant2_kernel() {
    extern __shared__ float srow[];
    __shared__ float red[32];
    const int t = blockIdx.x;
    const float4* ir = (const float4*)(g_inter + (size_t)t * IDIM);
    float amax = 0.f;
    for (int i = threadIdx.x; i < IDIM / 4; i += blockDim.x) {
        float4 v = ir[i];
        ((float4*)srow)[i] = v;
        amax = fmaxf(amax, fmaxf(fmaxf(fabsf(v.x), fabsf(v.y)), fmaxf(fabsf(v.z), fabsf(v.w))));
    }
    __syncthreads();
    amax = block_max(amax, red);
    const float scale = fmaxf(amax * (1.0f / 127.0f), 1e-8f);
    if (threadIdx.x == 0) g_s2[t] = scale;
    const float inv = 1.0f / scale;
    for (int i = threadIdx.x; i < IDIM; i += blockDim.x) {
        float q = rintf(srow[i] * inv);
        q = fminf(fmaxf(q, -128.f), 127.f);
        g_q28[(size_t)t * IDIM + i] = (int8_t)(int)q;
    }
}

// ---------------------------------------------------------------------------
// Host launcher
// ---------------------------------------------------------------------------
extern "C" void kernel_launch(void* const* d_in, const int* in_sizes, int n_in,
                              void* d_out, int out_size) {
    const float* x  = (const float*)d_in[0];
    const float* wg = (const float*)d_in[1];
    const float* wu = (const float*)d_in[2];
    const float* wd = (const float*)d_in[3];
    float* out = (float*)d_out;
    (void)in_sizes; (void)n_in; (void)out_size;

    void *p_xq, *p_xs, *p_sg, *p_inter, *p_q2, *p_s2;
    void *p_g1, *p_g2, *p_g3, *p_u1, *p_u2, *p_u3, *p_d1, *p_d2, *p_d3;
    void *p_gs, *p_us, *p_ds;
    cudaGetSymbolAddress(&p_xq, g_xq8);   cudaGetSymbolAddress(&p_xs, g_xscale);
    cudaGetSymbolAddress(&p_sg, g_sgate); cudaGetSymbolAddress(&p_inter, g_inter);
    cudaGetSymbolAddress(&p_q2, g_q28);   cudaGetSymbolAddress(&p_s2, g_s2);
    cudaGetSymbolAddress(&p_g1, g_wg1);   cudaGetSymbolAddress(&p_g2, g_wg2);
    cudaGetSymbolAddress(&p_g3, g_wg3);   cudaGetSymbolAddress(&p_u1, g_wu1);
    cudaGetSymbolAddress(&p_u2, g_wu2);   cudaGetSymbolAddress(&p_u3, g_wu3);
    cudaGetSymbolAddress(&p_d1, g_wd1);   cudaGetSymbolAddress(&p_d2, g_wd2);
    cudaGetSymbolAddress(&p_d3, g_wd3);   cudaGetSymbolAddress(&p_gs, g_wgs);
    cudaGetSymbolAddress(&p_us, g_wus);   cudaGetSymbolAddress(&p_ds, g_wds);

    const int smem_gemm = 3 * 4 * 8192 + 128;        // 98432
    const int smem_row  = IDIM * (int)sizeof(float); // 57344
    cudaFuncSetAttribute(igemm_kernel<0>, cudaFuncAttributeMaxDynamicSharedMemorySize, smem_gemm);
    cudaFuncSetAttribute(igemm_kernel<1>, cudaFuncAttributeMaxDynamicSharedMemorySize, smem_gemm);
    cudaFuncSetAttribute(igemm_kernel<2>, cudaFuncAttributeMaxDynamicSharedMemorySize, smem_gemm);
    cudaFuncSetAttribute(split3_kernel,  cudaFuncAttributeMaxDynamicSharedMemorySize, smem_row);
    cudaFuncSetAttribute(quant2_kernel,  cudaFuncAttributeMaxDynamicSharedMemorySize, smem_row);

    // 1) 3-level int8 weight expansions
    split3_kernel<<<IDIM, 256, HDIM * 4>>>(wg, (int8_t*)p_g1, (int8_t*)p_g2,
                                           (int8_t*)p_g3, (float*)p_gs, HDIM);
    split3_kernel<<<IDIM, 256, HDIM * 4>>>(wu, (int8_t*)p_u1, (int8_t*)p_u2,
                                           (int8_t*)p_u3, (float*)p_us, HDIM);
    split3_kernel<<<HDIM, 256, smem_row>>>(wd, (int8_t*)p_d1, (int8_t*)p_d2,
                                           (int8_t*)p_d3, (float*)p_ds, IDIM);

    // 2) per-token fake-quant of x -> int8
    quant_x_kernel<<<M_TOK, 256>>>(x);

    // 3) gate GEMM -> silu(gate)
    dim3 g1(M_TOK / 128, IDIM / 128);   // (32, 112), m fastest
    igemm_kernel<1><<<g1, 256, smem_gemm>>>(
        (const int8_t*)p_xq, (const int8_t*)p_g1, (const int8_t*)p_g2,
        (const int8_t*)p_g3, (const float*)p_gs, (const float*)p_xs,
        nullptr, (float*)p_sg, HDIM, IDIM);

    // 4) up GEMM, epilogue multiplies silu(gate) -> inter
    igemm_kernel<2><<<g1, 256, smem_gemm>>>(
        (const int8_t*)p_xq, (const int8_t*)p_u1, (const int8_t*)p_u2,
        (const int8_t*)p_u3, (const float*)p_us, (const float*)p_xs,
        (const float*)p_sg, (float*)p_inter, HDIM, IDIM);

    // 5) fake-quant of inter -> int8
    quant2_kernel<<<M_TOK, 512, smem_row>>>();

    // 6) down GEMM -> out
    dim3 g3(M_TOK / 128, HDIM / 128);   // (32, 32)
    igemm_kernel<0><<<g3, 256, smem_gemm>>>(
        (const int8_t*)p_q2, (const int8_t*)p_d1, (const int8_t*)p_d2,
        (const int8_t*)p_d3, (const float*)p_ds, (const float*)p_s2,
        nullptr, out, IDIM, HDIM);
}

// round 10
// speedup vs baseline: 5.6506x; 5.6506x over previous
#include <cuda_runtime.h>
#include <cuda_bf16.h>
#include <cuda_fp16.h>
#include <cstdint>

// Problem dims (fixed by the dataset)
#define M_TOK 4096            // B*S
#define HDIM  4096
#define IDIM  14336

// ---------------------------------------------------------------------------
// Device scratch (allocation-free rule: __device__ globals)
// ---------------------------------------------------------------------------
__device__ __nv_bfloat16 g_xq[(size_t)M_TOK * HDIM];      // quantized x (ints in bf16)
__device__ float         g_xscale[M_TOK];
__device__ float         g_inter[(size_t)M_TOK * IDIM];   // silu(gate)*up, fp32
__device__ __half        g_q2h[(size_t)M_TOK * IDIM];     // quantized inter (ints in fp16)
__device__ float         g_s2[M_TOK];
__device__ __nv_bfloat16 g_wg_hi[(size_t)IDIM * HDIM];
__device__ __nv_bfloat16 g_wg_lo[(size_t)IDIM * HDIM];
__device__ __nv_bfloat16 g_wu_hi[(size_t)IDIM * HDIM];
__device__ __nv_bfloat16 g_wu_lo[(size_t)IDIM * HDIM];
__device__ __half        g_wd_h [(size_t)HDIM * IDIM];    // down weights, fp16 single

// ---------------------------------------------------------------------------
// PTX helpers (all legal at compute_103 base target)
// ---------------------------------------------------------------------------
__device__ __forceinline__ uint32_t smem_u32(const void* p) {
    uint32_t a;
    asm("{ .reg .u64 t; cvta.to.shared.u64 t, %1; cvt.u32.u64 %0, t; }" : "=r"(a) : "l"(p));
    return a;
}
__device__ __forceinline__ void cp_async16(uint32_t saddr, const void* g) {
    asm volatile("cp.async.cg.shared.global [%0], [%1], 16;\n" :: "r"(saddr), "l"(g));
}
__device__ __forceinline__ void cp_commit() { asm volatile("cp.async.commit_group;\n"); }
template<int N> __device__ __forceinline__ void cp_wait() {
    asm volatile("cp.async.wait_group %0;\n" :: "n"(N));
}
__device__ __forceinline__ void ldsm_x4(uint32_t* r, uint32_t addr) {
    asm volatile("ldmatrix.sync.aligned.m8n8.x4.shared.b16 {%0,%1,%2,%3}, [%4];"
                 : "=r"(r[0]), "=r"(r[1]), "=r"(r[2]), "=r"(r[3]) : "r"(addr));
}
template<bool FP16_T>
__device__ __forceinline__ void mma16816(float* c, const uint32_t* a, uint32_t b0, uint32_t b1) {
    if (FP16_T) {
        asm volatile(
            "mma.sync.aligned.m16n8k16.row.col.f32.f16.f16.f32 "
            "{%0,%1,%2,%3},{%4,%5,%6,%7},{%8,%9},{%0,%1,%2,%3};\n"
            : "+f"(c[0]), "+f"(c[1]), "+f"(c[2]), "+f"(c[3])
            : "r"(a[0]), "r"(a[1]), "r"(a[2]), "r"(a[3]), "r"(b0), "r"(b1));
    } else {
        asm volatile(
            "mma.sync.aligned.m16n8k16.row.col.f32.bf16.bf16.f32 "
            "{%0,%1,%2,%3},{%4,%5,%6,%7},{%8,%9},{%0,%1,%2,%3};\n"
            : "+f"(c[0]), "+f"(c[1]), "+f"(c[2]), "+f"(c[3])
            : "r"(a[0]), "r"(a[1]), "r"(a[2]), "r"(a[3]), "r"(b0), "r"(b1));
    }
}

// ---------------------------------------------------------------------------
// Templated NT GEMM, BM=128 x BN=128 x BK=64, 8 warps (4m x 2n), warp 32x64.
// NMAT B-matrices share the A tile; pairs (2i,2i+1) accumulate into acc[i]
// (hi+lo share an accumulator). SWIGLU epilogue (NMAT=4):
//   C = silu(xs*accG) * (xs*accU).  Else: C = rowscale*acc[0].
// SMEM: XOR-swizzled 128B rows; cp.async loads, ldmatrix.x4 fragments.
// ---------------------------------------------------------------------------
template<int NMAT, bool SWIGLU, bool FP16_T, int MINB>
__global__ void __launch_bounds__(256, MINB)
hgemm_kernel(const uint16_t* __restrict__ A,
             const uint16_t* __restrict__ B0,
             const uint16_t* __restrict__ B1,
             const uint16_t* __restrict__ B2,
             const uint16_t* __restrict__ B3,
             const float* __restrict__ rowscale,
             float* __restrict__ Cout,
             int K, int N)
{
    constexpr int TILE  = 16384;                 // 128 rows * 128B
    constexpr int STAGE = (1 + NMAT) * TILE;
    constexpr int NACC  = (NMAT + 1) / 2;

    extern __shared__ char smem_raw[];
    const uint32_t sb = (smem_u32(smem_raw) + 127u) & ~127u;

    const int tid  = threadIdx.x;
    const int warp = tid >> 5;
    const int lane = tid & 31;
    const int wm = warp & 3;
    const int wn = warp >> 2;
    const int bm = blockIdx.x * 128;
    const int bn = blockIdx.y * 128;

    const uint16_t* Bs[4] = {B0, B1, B2, B3};

    float acc[NACC][2][8][4];
    #pragma unroll
    for (int q = 0; q < NACC; q++)
        #pragma unroll
        for (int a = 0; a < 2; a++)
            #pragma unroll
            for (int b = 0; b < 8; b++)
                #pragma unroll
                for (int c = 0; c < 4; c++) acc[q][a][b][c] = 0.f;

    const int KT = K >> 6;   // BK=64

    auto load_stage = [&](int kt, int s) {
        const int k0 = kt * 64;
        #pragma unroll
        for (int i = 0; i < 4; i++) {
            int id  = tid + i * 256;
            int row = id >> 3, c = id & 7;
            uint32_t dst = sb + s * STAGE + row * 128 + (((c ^ (row & 7)) << 4));
            cp_async16(dst, A + (size_t)(bm + row) * K + k0 + c * 8);
        }
        #pragma unroll
        for (int m = 0; m < NMAT; m++) {
            #pragma unroll
            for (int i = 0; i < 4; i++) {
                int id  = tid + i * 256;
                int row = id >> 3, c = id & 7;
                uint32_t dst = sb + s * STAGE + (1 + m) * TILE + row * 128
                             + (((c ^ (row & 7)) << 4));
                cp_async16(dst, Bs[m] + (size_t)(bn + row) * K + k0 + c * 8);
            }
        }
    };

    const int la7 = lane & 7;
    uint32_t a_row[2], b_row[4];
    #pragma unroll
    for (int mi = 0; mi < 2; mi++)
        a_row[mi] = (uint32_t)(wm * 32 + mi * 16 + la7 + ((lane >> 3) & 1) * 8) * 128;
    #pragma unroll
    for (int p = 0; p < 4; p++)
        b_row[p] = (uint32_t)(wn * 64 + p * 16 + la7 + (lane >> 4) * 8) * 128;
    const int kca = (lane >> 4);
    const int kcb = ((lane >> 3) & 1);

    load_stage(0, 0);
    cp_commit();

    for (int kt = 0; kt < KT; kt++) {
        cp_wait<0>();
        __syncthreads();
        if (kt + 1 < KT) load_stage(kt + 1, (kt + 1) & 1);
        cp_commit();

        const uint32_t base = sb + (kt & 1) * STAGE;
        #pragma unroll
        for (int kk = 0; kk < 4; kk++) {
            const uint32_t offa = (uint32_t)(((kk * 2 + kca) ^ la7) << 4);
            const uint32_t offb = (uint32_t)(((kk * 2 + kcb) ^ la7) << 4);
            uint32_t afr[2][4];
            ldsm_x4(afr[0], base + a_row[0] + offa);
            ldsm_x4(afr[1], base + a_row[1] + offa);
            #pragma unroll
            for (int p = 0; p < 4; p++) {
                #pragma unroll
                for (int m = 0; m < NMAT; m++) {
                    uint32_t bfr[4];
                    ldsm_x4(bfr, base + (1 + m) * TILE + b_row[p] + offb);
                    float* c0 = acc[m >> 1][0][2 * p];
                    float* c1 = acc[m >> 1][1][2 * p];
                    float* c2 = acc[m >> 1][0][2 * p + 1];
                    float* c3 = acc[m >> 1][1][2 * p + 1];
                    mma16816<FP16_T>(c0, afr[0], bfr[0], bfr[1]);
                    mma16816<FP16_T>(c1, afr[1], bfr[0], bfr[1]);
                    mma16816<FP16_T>(c2, afr[0], bfr[2], bfr[3]);
                    mma16816<FP16_T>(c3, afr[1], bfr[2], bfr[3]);
                }
            }
        }
    }

    // epilogue
    #pragma unroll
    for (int mi = 0; mi < 2; mi++) {
        const int r0 = bm + wm * 32 + mi * 16 + (lane >> 2);
        const float s0 = rowscale[r0];
        const float s1 = rowscale[r0 + 8];
        #pragma unroll
        for (int ni = 0; ni < 8; ni++) {
            const int col = bn + wn * 64 + ni * 8 + (lane & 3) * 2;
            if (SWIGLU) {
                float g0 = acc[0][mi][ni][0] * s0, g1 = acc[0][mi][ni][1] * s0;
                float u0 = acc[1][mi][ni][0] * s0, u1 = acc[1][mi][ni][1] * s0;
                float v0 = __fdividef(g0, 1.f + expf(-g0)) * u0;
                float v1 = __fdividef(g1, 1.f + expf(-g1)) * u1;
                *(float2*)&Cout[(size_t)r0 * N + col] = make_float2(v0, v1);
                float g2 = acc[0][mi][ni][2] * s1, g3 = acc[0][mi][ni][3] * s1;
                float u2 = acc[1][mi][ni][2] * s1, u3 = acc[1][mi][ni][3] * s1;
                float v2 = __fdividef(g2, 1.f + expf(-g2)) * u2;
                float v3 = __fdividef(g3, 1.f + expf(-g3)) * u3;
                *(float2*)&Cout[(size_t)(r0 + 8) * N + col] = make_float2(v2, v3);
            } else {
                *(float2*)&Cout[(size_t)r0 * N + col] =
                    make_float2(acc[0][mi][ni][0] * s0, acc[0][mi][ni][1] * s0);
                *(float2*)&Cout[(size_t)(r0 + 8) * N + col] =
                    make_float2(acc[0][mi][ni][2] * s1, acc[0][mi][ni][3] * s1);
            }
        }
    }
}

// ---------------------------------------------------------------------------
// Weight split fp32 -> bf16 hi/lo (vectorized)
// ---------------------------------------------------------------------------
__global__ void split_one_kernel(const float4* __restrict__ src,
                                 __nv_bfloat162* __restrict__ hi,
                                 __nv_bfloat162* __restrict__ lo, int n4) {
    const int stride = gridDim.x * blockDim.x;
    for (int i = blockIdx.x * blockDim.x + threadIdx.x; i < n4; i += stride) {
        float4 w = src[i];
        __nv_bfloat16 hx = __float2bfloat16_rn(w.x);
        __nv_bfloat16 hy = __float2bfloat16_rn(w.y);
        __nv_bfloat16 hz = __float2bfloat16_rn(w.z);
        __nv_bfloat16 hw = __float2bfloat16_rn(w.w);
        hi[2*i]   = __halves2bfloat162(hx, hy);
        hi[2*i+1] = __halves2bfloat162(hz, hw);
        lo[2*i]   = __halves2bfloat162(__float2bfloat16_rn(w.x - __bfloat162float(hx)),
                                       __float2bfloat16_rn(w.y - __bfloat162float(hy)));
        lo[2*i+1] = __halves2bfloat162(__float2bfloat16_rn(w.z - __bfloat162float(hz)),
                                       __float2bfloat16_rn(w.w - __bfloat162float(hw)));
    }
}

// ---------------------------------------------------------------------------
// fp32 -> fp16 convert (down weights)
// ---------------------------------------------------------------------------
__global__ void conv_half_kernel(const float4* __restrict__ src,
                                 __half2* __restrict__ dst, int n4) {
    const int stride = gridDim.x * blockDim.x;
    for (int i = blockIdx.x * blockDim.x + threadIdx.x; i < n4; i += stride) {
        float4 w = src[i];
        dst[2*i]   = __floats2half2_rn(w.x, w.y);
        dst[2*i+1] = __floats2half2_rn(w.z, w.w);
    }
}

// ---------------------------------------------------------------------------
// Block max-reduce
// ---------------------------------------------------------------------------
__device__ __forceinline__ float block_max(float v, float* red) {
    #pragma unroll
    for (int o = 16; o; o >>= 1) v = fmaxf(v, __shfl_xor_sync(0xFFFFFFFFu, v, o));
    if ((threadIdx.x & 31) == 0) red[threadIdx.x >> 5] = v;
    __syncthreads();
    if (threadIdx.x < 32) {
        float w = (threadIdx.x < (blockDim.x >> 5)) ? red[threadIdx.x] : 0.f;
        #pragma unroll
        for (int o = 16; o; o >>= 1) w = fmaxf(w, __shfl_xor_sync(0xFFFFFFFFu, w, o));
        if (threadIdx.x == 0) red[0] = w;
    }
    __syncthreads();
    return red[0];
}

// ---------------------------------------------------------------------------
// Per-token fake-quant of x -> bf16 ints (row cached in smem)
// ---------------------------------------------------------------------------
__global__ void quant_x_kernel(const float* __restrict__ x) {
    __shared__ float red[32];
    __shared__ float row[HDIM];
    const int t = blockIdx.x;
    const float4* xr = (const float4*)(x + (size_t)t * HDIM);
    float amax = 0.f;
    for (int i = threadIdx.x; i < HDIM / 4; i += blockDim.x) {
        float4 v = xr[i];
        ((float4*)row)[i] = v;
        amax = fmaxf(amax, fmaxf(fmaxf(fabsf(v.x), fabsf(v.y)), fmaxf(fabsf(v.z), fabsf(v.w))));
    }
    __syncthreads();
    amax = block_max(amax, red);
    const float scale = fmaxf(amax * (1.0f / 127.0f), 1e-8f);
    if (threadIdx.x == 0) g_xscale[t] = scale;
    const float inv = 1.0f / scale;
    for (int i = threadIdx.x; i < HDIM; i += blockDim.x) {
        float q = rintf(row[i] * inv);
        q = fminf(fmaxf(q, -128.f), 127.f);
        g_xq[(size_t)t * HDIM + i] = __float2bfloat16_rn(q);
    }
}

// ---------------------------------------------------------------------------
// Per-token fake-quant of inter -> fp16 ints
// ---------------------------------------------------------------------------
__global__ void quant2_kernel() {
    extern __shared__ float srow[];    // IDIM floats
    __shared__ float red[32];
    const int t = blockIdx.x;
    const float4* ir = (const float4*)(g_inter + (size_t)t * IDIM);
    float amax = 0.f;
    for (int i = threadIdx.x; i < IDIM / 4; i += blockDim.x) {
        float4 v = ir[i];
        ((float4*)srow)[i] = v;
        amax = fmaxf(amax, fmaxf(fmaxf(fabsf(v.x), fabsf(v.y)), fmaxf(fabsf(v.z), fabsf(v.w))));
    }
    __syncthreads();
    amax = block_max(amax, red);
    const float scale = fmaxf(amax * (1.0f / 127.0f), 1e-8f);
    if (threadIdx.x == 0) g_s2[t] = scale;
    const float inv = 1.0f / scale;
    for (int i = threadIdx.x; i < IDIM; i += blockDim.x) {
        float q = rintf(srow[i] * inv);
        q = fminf(fmaxf(q, -128.f), 127.f);
        g_q2h[(size_t)t * IDIM + i] = __float2half_rn(q);
    }
}

// ---------------------------------------------------------------------------
// Host launcher
// ---------------------------------------------------------------------------
extern "C" void kernel_launch(void* const* d_in, const int* in_sizes, int n_in,
                              void* d_out, int out_size) {
    const float* x  = (const float*)d_in[0];
    const float* wg = (const float*)d_in[1];
    const float* wu = (const float*)d_in[2];
    const float* wd = (const float*)d_in[3];
    float* out = (float*)d_out;
    (void)in_sizes; (void)n_in; (void)out_size;

    void *p_xq, *p_xs, *p_inter, *p_q2, *p_s2;
    void *p_wgh, *p_wgl, *p_wuh, *p_wul, *p_wdh;
    cudaGetSymbolAddress(&p_xq, g_xq);      cudaGetSymbolAddress(&p_xs, g_xscale);
    cudaGetSymbolAddress(&p_inter, g_inter);
    cudaGetSymbolAddress(&p_q2, g_q2h);     cudaGetSymbolAddress(&p_s2, g_s2);
    cudaGetSymbolAddress(&p_wgh, g_wg_hi);  cudaGetSymbolAddress(&p_wgl, g_wg_lo);
    cudaGetSymbolAddress(&p_wuh, g_wu_hi);  cudaGetSymbolAddress(&p_wul, g_wu_lo);
    cudaGetSymbolAddress(&p_wdh, g_wd_h);

    const int smem_fused = 2 * 5 * 16384 + 128;   // 163968
    const int smem_down  = 2 * 2 * 16384 + 128;   // 65664
    const int smem_q2    = IDIM * (int)sizeof(float);
    cudaFuncSetAttribute((const void*)hgemm_kernel<4, true, false, 1>,
                         cudaFuncAttributeMaxDynamicSharedMemorySize, smem_fused);
    cudaFuncSetAttribute((const void*)hgemm_kernel<1, false, true, 2>,
                         cudaFuncAttributeMaxDynamicSharedMemorySize, smem_down);
    cudaFuncSetAttribute(quant2_kernel,
                         cudaFuncAttributeMaxDynamicSharedMemorySize, smem_q2);

    // 1) gate/up weights -> bf16 hi/lo; down weights -> fp16
    const int n4 = (IDIM / 4) * HDIM;
    split_one_kernel<<<1024, 256>>>((const float4*)wg, (__nv_bfloat162*)p_wgh,
                                    (__nv_bfloat162*)p_wgl, n4);
    split_one_kernel<<<1024, 256>>>((const float4*)wu, (__nv_bfloat162*)p_wuh,
                                    (__nv_bfloat162*)p_wul, n4);
    conv_half_kernel<<<1024, 256>>>((const float4*)wd, (__half2*)p_wdh, n4);

    // 2) per-token fake-quant of x
    quant_x_kernel<<<M_TOK, 256>>>(x);

    // 3) fused gate/up GEMM (bf16 hi+lo) + SwiGLU epilogue -> inter
    dim3 g1(M_TOK / 128, IDIM / 128);   // (32, 112), m fastest
    hgemm_kernel<4, true, false, 1><<<g1, 256, smem_fused>>>(
        (const uint16_t*)p_xq,
        (const uint16_t*)p_wgh, (const uint16_t*)p_wgl,
        (const uint16_t*)p_wuh, (const uint16_t*)p_wul,
        (const float*)p_xs, (float*)p_inter, HDIM, IDIM);

    // 4) fake-quant of inter -> fp16 ints
    quant2_kernel<<<M_TOK, 512, smem_q2>>>();

    // 5) down GEMM (fp16 single) -> out
    dim3 g3(M_TOK / 128, HDIM / 128);   // (32, 32)
    hgemm_kernel<1, false, true, 2><<<g3, 256, smem_down>>>(
        (const uint16_t*)p_q2,
        (const uint16_t*)p_wdh, (const uint16_t*)p_wdh,
        (const uint16_t*)p_wdh, (const uint16_t*)p_wdh,
        (const float*)p_s2, out, IDIM, HDIM);
}